// round 16
// baseline (speedup 1.0000x reference)
#include <cuda_runtime.h>
#include <cuda_bf16.h>
#include <cstdint>
#include <cstddef>

// ---------------- problem constants ----------------
#define B_     64
#define NKV    8192
#define D      64
#define NQ     8
#define C32    32
#define EPS_A  1e-8f
#define TT     64

// pass 0 (fp32 input) config
#define NCH0   32
#define TPC0   256
#define NT0    (TPC0 / TT)      // 4
#define NMAIN0 (B_ * NCH0)      // 2048

// pass 1,2 (cached bf16) config
#define NCH1   16
#define TPC1   512
#define NT1    (TPC1 / TT)      // 8
#define NMAIN1 (B_ * NCH1)      // 1024

#define NSLOT  (B_ * 4)         // 256 slot CTAs (4 per batch, 2 slots each)

#define SXF 68
#define SXBU 36
#define SATR 40
#define WFU 36

// ---------------- device scratch ----------------
__device__ uint32_t g_wfoldu[B_ * C32 * 32];          // bf16x2 Wfold
__device__ uint32_t g_lnx  [B_ * NKV * 32];           // bf16x2 lnX cache
__device__ float    g_part [B_ * NCH0 * C32 * D];     // per-chunk S' partials
__device__ float    g_sap  [B_ * NCH0 * C32];         // per-chunk colsum partials
__device__ float    g_slots[B_ * NQ * D];             // working slots
__device__ int      g_cnt  [B_];                      // chunk arrival counters (cumulative)
__device__ int      g_tws  [B_];                      // slot-tail (Wfold ready) counters
__device__ float    g_wihT [64 * 192];                // W_ih^T
__device__ float    g_whhT [64 * 192];                // W_hh^T
__device__ float    g_wkT  [64 * 64];                 // Wk^T

// ---------------- helpers ----------------
__device__ __forceinline__ uint32_t pack_bf16x2(float lo, float hi) {
    uint32_t r;
    asm("cvt.rn.bf16x2.f32 %0, %1, %2;" : "=r"(r) : "f"(hi), "f"(lo));
    return r;
}
__device__ __forceinline__ void mma16(float c[4],
                                      uint32_t a0, uint32_t a1, uint32_t a2, uint32_t a3,
                                      uint32_t b0, uint32_t b1) {
    asm volatile(
        "mma.sync.aligned.m16n8k16.row.col.f32.bf16.bf16.f32 "
        "{%0,%1,%2,%3},{%4,%5,%6,%7},{%8,%9},{%0,%1,%2,%3};"
        : "+f"(c[0]), "+f"(c[1]), "+f"(c[2]), "+f"(c[3])
        : "r"(a0), "r"(a1), "r"(a2), "r"(a3), "r"(b0), "r"(b1));
}
__device__ __forceinline__ void ldm_x4t(uint32_t& r0, uint32_t& r1, uint32_t& r2, uint32_t& r3,
                                        uint32_t addr) {
    asm volatile("ldmatrix.sync.aligned.m8n8.x4.trans.shared.b16 {%0,%1,%2,%3}, [%4];"
                 : "=r"(r0), "=r"(r1), "=r"(r2), "=r"(r3) : "r"(addr));
}
__device__ __forceinline__ void cp_async16(uint32_t smem_addr, const void* gptr) {
    asm volatile("cp.async.cg.shared.global [%0], [%1], 16;"
                 :: "r"(smem_addr), "l"(gptr));
}
__device__ __forceinline__ void cp_commit() { asm volatile("cp.async.commit_group;"); }
__device__ __forceinline__ void cp_wait0()  { asm volatile("cp.async.wait_group 0;"); }
__device__ __forceinline__ float sigm(float x) { return 1.f / (1.f + __expf(-x)); }

__device__ __forceinline__ void spin_ge(const int* addr, int tgt) {
    int v = 0;
    while (v < tgt) {
        asm volatile("ld.acquire.gpu.global.s32 %0, [%1];" : "=r"(v) : "l"(addr));
        if (v < tgt) __nanosleep(200);
    }
}

__device__ __forceinline__ void signal_done(int b, int tid) {
    __threadfence();
    __syncthreads();
    if (tid == 0) atomicAdd(&g_cnt[b], 1);
}

// =====================================================================
// Slot-update tail: 4 CTAs per batch (2 slots each), 128 threads.
// Non-last tails bump g_tws[b] after publishing the next Wfold.
// =====================================================================
__device__ void slot_tail(float* S, int sb, int tgt, int nch, int last,
                          const float* __restrict__ Wq,
                          const float* __restrict__ Wv,
                          const float* __restrict__ b_ih, const float* __restrict__ b_hh,
                          const float* __restrict__ lns_g, const float* __restrict__ lns_b,
                          const float* __restrict__ lnm_g, const float* __restrict__ lnm_b,
                          const float* __restrict__ W1, const float* __restrict__ b1v,
                          const float* __restrict__ W2, const float* __restrict__ b2v,
                          float* __restrict__ out_slots)
{
    const int b = sb >> 2;
    const int p = sb & 3;            // slot pair: q in {2p, 2p+1}
    const int tid = threadIdx.x;
    const int w = tid >> 5, lane = tid & 31;

    float* s_sax = S;                // [8][64]
    float* s_sa  = S + 512;          // [8]
    float* s_sl  = S + 520;          // [2][64]
    float* s_up  = S + 648;          // [2][64]
    float* s_gx  = S + 776;          // [2][192]
    float* s_gh  = S + 1160;         // [2][192]
    float* s_ln  = S + 1544;         // [2][64]
    float* s_hid = S + 1672;         // [2][128]

    if (tid == 0) spin_ge(g_cnt + b, tgt);
    __syncthreads();

    #pragma unroll
    for (int k = 0; k < 4; k++) {
        int o = tid + 128 * k;
        int lr = o >> 6, e = o & 63;
        int h = lr >> 1, q = 2 * p + (lr & 1);
        int c = h * 8 + q;
        const float* gp = g_part + ((size_t)b * NCH0 * C32 + c) * D + e;
        float a0 = 0.f, a1 = 0.f;
        for (int ch = 0; ch < nch; ch += 2) {
            a0 += gp[(size_t)ch * (C32 * D)];
            a1 += gp[(size_t)(ch + 1) * (C32 * D)];
        }
        s_sax[lr * 64 + e] = a0 + a1;
    }
    if (tid < 8) {
        int h = tid >> 1, q = 2 * p + (tid & 1);
        int c = h * 8 + q;
        float s = 0.f;
        for (int ch = 0; ch < nch; ch++)
            s += g_sap[(b * NCH0 + ch) * C32 + c];
        s_sa[tid] = s;
    }
    {
        int qi = tid >> 6, dd = tid & 63;
        s_sl[qi * 64 + dd] = g_slots[(b * NQ + 2 * p + qi) * 64 + dd];
    }
    __syncthreads();

    {
        int qi = tid >> 6, hd = tid & 63, h = hd >> 4;
        const float* sr = s_sax + (h * 2 + qi) * 64;
        float a0 = 0.f, a1 = 0.f;
        #pragma unroll
        for (int e = 0; e < 64; e += 2) {
            a0 = fmaf(sr[e],     Wv[e * 64 + hd],       a0);
            a1 = fmaf(sr[e + 1], Wv[(e + 1) * 64 + hd], a1);
        }
        s_up[qi * 64 + hd] = (a0 + a1) / s_sa[h * 2 + qi];
    }
    __syncthreads();

    #pragma unroll
    for (int k = 0; k < 3; k++) {
        int o = tid + 128 * k;
        int qi = (o >= 192) ? 1 : 0;
        int cc = o - 192 * qi;
        const float* xu = s_up + qi * 64;
        const float* xs = s_sl + qi * 64;
        float gx0 = 0.f, gx1 = 0.f, gh0 = 0.f, gh1 = 0.f;
        #pragma unroll 8
        for (int dd = 0; dd < 64; dd += 2) {
            gx0 = fmaf(xu[dd],     g_wihT[dd * 192 + cc],       gx0);
            gx1 = fmaf(xu[dd + 1], g_wihT[(dd + 1) * 192 + cc], gx1);
            gh0 = fmaf(xs[dd],     g_whhT[dd * 192 + cc],       gh0);
            gh1 = fmaf(xs[dd + 1], g_whhT[(dd + 1) * 192 + cc], gh1);
        }
        s_gx[qi * 192 + cc] = gx0 + gx1 + b_ih[cc];
        s_gh[qi * 192 + cc] = gh0 + gh1 + b_hh[cc];
    }
    __syncthreads();

    {
        int qi = tid >> 6, dd = tid & 63;
        float r = sigm(s_gx[qi * 192 + dd]        + s_gh[qi * 192 + dd]);
        float z = sigm(s_gx[qi * 192 + 64 + dd]   + s_gh[qi * 192 + 64 + dd]);
        float n = tanhf(s_gx[qi * 192 + 128 + dd] + r * s_gh[qi * 192 + 128 + dd]);
        s_up[qi * 64 + dd] = (1.f - z) * n + z * s_sl[qi * 64 + dd];
    }
    __syncthreads();

    if (w < 2) {
        float x0 = s_up[w * 64 + lane], x1 = s_up[w * 64 + 32 + lane];
        float s = x0 + x1, qq = x0 * x0 + x1 * x1;
        #pragma unroll
        for (int off = 16; off; off >>= 1) {
            s  += __shfl_xor_sync(0xffffffffu, s,  off);
            qq += __shfl_xor_sync(0xffffffffu, qq, off);
        }
        float m = s * (1.f / 64.f);
        float rs = rsqrtf(qq * (1.f / 64.f) - m * m + 1e-5f);
        s_ln[w * 64 + lane]      = (x0 - m) * rs * lnm_g[lane]      + lnm_b[lane];
        s_ln[w * 64 + 32 + lane] = (x1 - m) * rs * lnm_g[lane + 32] + lnm_b[lane + 32];
    }
    __syncthreads();

    #pragma unroll
    for (int k = 0; k < 2; k++) {
        int o = tid + 128 * k;
        int qi = o >> 7, j = o & 127;
        const float* xl = s_ln + qi * 64;
        float a0 = 0.f, a1 = 0.f;
        #pragma unroll 8
        for (int dd = 0; dd < 64; dd += 2) {
            a0 = fmaf(xl[dd],     W1[dd * 128 + j],       a0);
            a1 = fmaf(xl[dd + 1], W1[(dd + 1) * 128 + j], a1);
        }
        s_hid[qi * 128 + j] = fmaxf(a0 + a1 + b1v[j], 0.f);
    }
    __syncthreads();

    {
        int qi = tid >> 6, dd = tid & 63;
        const float* hh = s_hid + qi * 128;
        float a0 = 0.f, a1 = 0.f;
        #pragma unroll 8
        for (int j = 0; j < 128; j += 2) {
            a0 = fmaf(hh[j],     W2[j * 64 + dd],       a0);
            a1 = fmaf(hh[j + 1], W2[(j + 1) * 64 + dd], a1);
        }
        float fin = s_up[qi * 64 + dd] + a0 + a1 + b2v[dd];
        s_sl[qi * 64 + dd] = fin;
        g_slots[(b * NQ + 2 * p + qi) * 64 + dd] = fin;
        if (last) out_slots[(b * NQ + 2 * p + qi) * 64 + dd] = fin;
    }
    __syncthreads();
    if (last) return;

    if (w < 2) {
        float x0 = s_sl[w * 64 + lane], x1 = s_sl[w * 64 + 32 + lane];
        float s = x0 + x1, qq = x0 * x0 + x1 * x1;
        #pragma unroll
        for (int off = 16; off; off >>= 1) {
            s  += __shfl_xor_sync(0xffffffffu, s,  off);
            qq += __shfl_xor_sync(0xffffffffu, qq, off);
        }
        float m = s * (1.f / 64.f);
        float rs = rsqrtf(qq * (1.f / 64.f) - m * m + 1e-5f);
        s_ln[w * 64 + lane]      = (x0 - m) * rs * lns_g[lane]      + lns_b[lane];
        s_ln[w * 64 + 32 + lane] = (x1 - m) * rs * lns_g[lane + 32] + lns_b[lane + 32];
    }
    __syncthreads();

    {
        int qi = tid >> 6, e = tid & 63;
        const float* xl = s_ln + qi * 64;
        float a0 = 0.f, a1 = 0.f;
        #pragma unroll 8
        for (int dd = 0; dd < 64; dd += 2) {
            a0 = fmaf(xl[dd],     Wq[dd * 64 + e],       a0);
            a1 = fmaf(xl[dd + 1], Wq[(dd + 1) * 64 + e], a1);
        }
        s_hid[qi * 64 + e] = a0 + a1;
    }
    __syncthreads();

    #pragma unroll
    for (int k = 0; k < 2; k++) {
        int o = tid + 128 * k;
        int lr = o >> 5, ep = o & 31;
        int h = lr >> 1, qi = lr & 1, q = 2 * p + qi, c = h * 8 + q;
        float a0 = 0.f, a1 = 0.f;
        #pragma unroll
        for (int dd = 0; dd < 16; dd++) {
            float qv = s_hid[qi * 64 + h * 16 + dd];
            float2 wk = ((const float2*)(g_wkT + (h * 16 + dd) * 64))[ep];
            a0 = fmaf(wk.x, qv, a0);
            a1 = fmaf(wk.y, qv, a1);
        }
        g_wfoldu[b * 1024 + c * 32 + ep] = pack_bf16x2(0.25f * a0, 0.25f * a1);
    }

    // publish Wfold: release + bump tail counter
    __threadfence();
    __syncthreads();
    if (tid == 0) atomicAdd(&g_tws[b], 1);
}

// =====================================================================
// Pass-0 fused kernel (unchanged from R14): 32x256-token chunks + tails
// =====================================================================
__global__ void __launch_bounds__(128, 4)
vslot_main(const float* __restrict__ inputs,
           const float* __restrict__ lng_g,
           const float* __restrict__ lnb_g,
           int tgt,
           const float* __restrict__ Wq,  const float* __restrict__ Wv,
           const float* __restrict__ b_ih, const float* __restrict__ b_hh,
           const float* __restrict__ lns_g, const float* __restrict__ lns_b,
           const float* __restrict__ lnm_g, const float* __restrict__ lnm_b,
           const float* __restrict__ W1, const float* __restrict__ b1v,
           const float* __restrict__ W2, const float* __restrict__ b2v,
           float* __restrict__ out_slots)
{
    extern __shared__ float sm[];

    if (blockIdx.x >= NMAIN0) {
        slot_tail(sm, blockIdx.x - NMAIN0, tgt, NCH0, 0, Wq, Wv, b_ih, b_hh,
                  lns_g, lns_b, lnm_g, lnm_b, W1, b1v, W2, b2v, out_slots);
        return;
    }

    float*          sxf0 = sm;
    float*          sxf1 = sxf0 + TT * SXF;
    uint32_t*       sxb  = (uint32_t*)(sxf1 + TT * SXF);
    __nv_bfloat16*  satr = (__nv_bfloat16*)(sxb + TT * SXBU);
    uint32_t*       satu = (uint32_t*)satr;
    uint32_t*       wfT  = satu + (TT * SATR / 2);
    float*          slng = (float*)(wfT + C32 * WFU);
    float*          slnb = slng + 64;

    const int b     = blockIdx.x >> 5;
    const int chunk = blockIdx.x & 31;
    const int n0    = chunk * TPC0;
    const int tid   = threadIdx.x;
    const int w     = tid >> 5;
    const int lane  = tid & 31;
    const int g     = lane >> 2;
    const int t     = lane & 3;
    const int r0    = w * 16 + g;

    for (int i = tid; i < C32 * 32; i += 128)
        wfT[(i >> 5) * WFU + (i & 31)] = g_wfoldu[b * 1024 + i];
    if (tid < 64) { slng[tid] = lng_g[tid]; slnb[tid] = lnb_g[tid]; }

    const float4* gbase = reinterpret_cast<const float4*>(
        inputs + ((size_t)b * NKV + n0) * D);
    uint32_t sxa[2];
    sxa[0] = (uint32_t)__cvta_generic_to_shared(sxf0);
    sxa[1] = (uint32_t)__cvta_generic_to_shared(sxf1);
    const uint32_t sat_s = (uint32_t)__cvta_generic_to_shared(satr);
    const uint32_t sxb_s = (uint32_t)__cvta_generic_to_shared(sxb);

    const int mblk = w & 1;
    const int ncol = (w >> 1) * 32;
    const int l = lane;
    const uint32_t aAddr = sat_s +
        (uint32_t)(((l & 7) + ((l >> 4) & 1) * 8) * (SATR * 2)
                   + (16 * mblk + ((l >> 3) & 1) * 8) * 2);
    const uint32_t bAddr = sxb_s +
        (uint32_t)((l & 15) * (SXBU * 4) + (ncol + ((l >> 4) & 1) * 8) * 2);

    #pragma unroll
    for (int k = 0; k < 8; k++) {
        int i = tid + 128 * k;
        cp_async16(sxa[0] + ((i >> 4) * SXF + (i & 15) * 4) * 4, gbase + i);
    }
    cp_commit();

    float c2[4][4];
    float colsum[4][2];
    #pragma unroll
    for (int a = 0; a < 4; a++) {
        #pragma unroll
        for (int i = 0; i < 4; i++) c2[a][i] = 0.f;
        colsum[a][0] = 0.f; colsum[a][1] = 0.f;
    }

    #pragma unroll
    for (int t4 = 0; t4 < NT0; t4++) {
        const float* sxf = (t4 & 1) ? sxf1 : sxf0;

        cp_wait0();
        __syncthreads();

        if (t4 + 1 < NT0) {
            const float4* gn = gbase + (size_t)(t4 + 1) * (TT * D / 4);
            uint32_t dst = sxa[(t4 + 1) & 1];
            #pragma unroll
            for (int k = 0; k < 8; k++) {
                int i = tid + 128 * k;
                cp_async16(dst + ((i >> 4) * SXF + (i & 15) * 4) * 4, gn + i);
            }
            cp_commit();
        }

        // ---- layernorm ----
        float2 x0[8], x1[8];
        float s0 = 0.f, q0 = 0.f, s1 = 0.f, q1 = 0.f;
        {
            const float* p0 = sxf + r0 * SXF + 2 * t;
            const float* p1 = p0 + 8 * SXF;
            #pragma unroll
            for (int m = 0; m < 8; m++) {
                x0[m] = *reinterpret_cast<const float2*>(p0 + 8 * m);
                x1[m] = *reinterpret_cast<const float2*>(p1 + 8 * m);
                s0 += x0[m].x + x0[m].y;
                q0 = fmaf(x0[m].x, x0[m].x, fmaf(x0[m].y, x0[m].y, q0));
                s1 += x1[m].x + x1[m].y;
                q1 = fmaf(x1[m].x, x1[m].x, fmaf(x1[m].y, x1[m].y, q1));
            }
        }
        s0 += __shfl_xor_sync(0xffffffffu, s0, 1);
        q0 += __shfl_xor_sync(0xffffffffu, q0, 1);
        s1 += __shfl_xor_sync(0xffffffffu, s1, 1);
        q1 += __shfl_xor_sync(0xffffffffu, q1, 1);
        s0 += __shfl_xor_sync(0xffffffffu, s0, 2);
        q0 += __shfl_xor_sync(0xffffffffu, q0, 2);
        s1 += __shfl_xor_sync(0xffffffffu, s1, 2);
        q1 += __shfl_xor_sync(0xffffffffu, q1, 2);
        float mu0 = s0 * (1.f / 64.f), mu1 = s1 * (1.f / 64.f);
        float rs0 = rsqrtf(fmaf(-mu0, mu0, q0 * (1.f / 64.f)) + 1e-5f);
        float rs1 = rsqrtf(fmaf(-mu1, mu1, q1 * (1.f / 64.f)) + 1e-5f);

        uint32_t v0p[8], v1p[8];
        {
            uint32_t* o0 = sxb + r0 * SXBU + t;
            uint32_t* o1 = o0 + 8 * SXBU;
            #pragma unroll
            for (int m = 0; m < 8; m++) {
                float2 gb = *reinterpret_cast<const float2*>(slng + 2 * t + 8 * m);
                float2 bb = *reinterpret_cast<const float2*>(slnb + 2 * t + 8 * m);
                float y00 = fmaf((x0[m].x - mu0) * rs0, gb.x, bb.x);
                float y01 = fmaf((x0[m].y - mu0) * rs0, gb.y, bb.y);
                float y10 = fmaf((x1[m].x - mu1) * rs1, gb.x, bb.x);
                float y11 = fmaf((x1[m].y - mu1) * rs1, gb.y, bb.y);
                v0p[m] = pack_bf16x2(y00, y01);
                v1p[m] = pack_bf16x2(y10, y11);
                o0[4 * m] = v0p[m];
                o1[4 * m] = v1p[m];
            }
        }

        // ---- GEMM1 ----
        float c1[4][4];
        #pragma unroll
        for (int j = 0; j < 4; j++)
            #pragma unroll
            for (int i = 0; i < 4; i++) c1[j][i] = 0.f;
        #pragma unroll
        for (int ks = 0; ks < 4; ks++) {
            uint32_t a0 = v0p[2 * ks],     a1 = v1p[2 * ks];
            uint32_t a2 = v0p[2 * ks + 1], a3 = v1p[2 * ks + 1];
            #pragma unroll
            for (int j = 0; j < 4; j++) {
                uint32_t b0 = wfT[(8 * j + g) * WFU + 8 * ks + t];
                uint32_t b1 = wfT[(8 * j + g) * WFU + 8 * ks + t + 4];
                mma16(c1[j], a0, a1, a2, a3, b0, b1);
            }
        }

        // ---- softmax ----
        float m0 = -1e30f, m1 = -1e30f;
        #pragma unroll
        for (int j = 0; j < 4; j++) {
            m0 = fmaxf(m0, fmaxf(c1[j][0], c1[j][1]));
            m1 = fmaxf(m1, fmaxf(c1[j][2], c1[j][3]));
        }
        m0 = fmaxf(m0, __shfl_xor_sync(0xffffffffu, m0, 1));
        m0 = fmaxf(m0, __shfl_xor_sync(0xffffffffu, m0, 2));
        m1 = fmaxf(m1, __shfl_xor_sync(0xffffffffu, m1, 1));
        m1 = fmaxf(m1, __shfl_xor_sync(0xffffffffu, m1, 2));
        float ss0 = 0.f, ss1 = 0.f;
        #pragma unroll
        for (int j = 0; j < 4; j++) {
            c1[j][0] = __expf(c1[j][0] - m0);
            c1[j][1] = __expf(c1[j][1] - m0);
            c1[j][2] = __expf(c1[j][2] - m1);
            c1[j][3] = __expf(c1[j][3] - m1);
            ss0 += c1[j][0] + c1[j][1];
            ss1 += c1[j][2] + c1[j][3];
        }
        ss0 += __shfl_xor_sync(0xffffffffu, ss0, 1);
        ss0 += __shfl_xor_sync(0xffffffffu, ss0, 2);
        ss1 += __shfl_xor_sync(0xffffffffu, ss1, 1);
        ss1 += __shfl_xor_sync(0xffffffffu, ss1, 2);
        float inv0 = 1.f / ss0, inv1 = 1.f / ss1;

        // ---- attn+eps -> satr + colsums ----
        #pragma unroll
        for (int j = 0; j < 4; j++) {
            float a00 = fmaf(c1[j][0], inv0, EPS_A);
            float a01 = fmaf(c1[j][1], inv0, EPS_A);
            float a10 = fmaf(c1[j][2], inv1, EPS_A);
            float a11 = fmaf(c1[j][3], inv1, EPS_A);
            satu[r0 * (SATR / 2) + 4 * j + t]       = pack_bf16x2(a00, a01);
            satu[(r0 + 8) * (SATR / 2) + 4 * j + t] = pack_bf16x2(a10, a11);
            colsum[j][0] += a00 + a10;
            colsum[j][1] += a01 + a11;
        }
        __syncthreads();

        // ---- GEMM2 ----
        #pragma unroll
        for (int ks = 0; ks < 4; ks++) {
            uint32_t a0, a1, a2, a3, f0, f1, f2, f3;
            ldm_x4t(a0, a1, a2, a3, aAddr + ks * (16 * SATR * 2));
            ldm_x4t(f0, f1, f2, f3, bAddr + ks * (16 * SXBU * 4));
            mma16(c2[0], a0, a1, a2, a3, f0, f1);
            mma16(c2[1], a0, a1, a2, a3, f2, f3);
            ldm_x4t(f0, f1, f2, f3, bAddr + ks * (16 * SXBU * 4) + 32);
            mma16(c2[2], a0, a1, a2, a3, f0, f1);
            mma16(c2[3], a0, a1, a2, a3, f2, f3);
        }

        // ---- dump bf16 lnX tile to cache ----
        {
            uint32_t* gl = g_lnx + ((size_t)b * NKV + n0 + t4 * TT) * 32;
            #pragma unroll
            for (int k = 0; k < 16; k++) {
                int i = tid + 128 * k;
                gl[i] = sxb[(i >> 5) * SXBU + (i & 31)];
            }
        }
    }

    // ---- epilogue ----
    {
        const int crow = 16 * mblk + g;
        float* pp = &g_part[(size_t)(b * NCH0 + chunk) * (C32 * D)];
        #pragma unroll
        for (int nb = 0; nb < 4; nb++) {
            int e0 = ncol + 8 * nb + 2 * t;
            pp[crow * D + e0]           = c2[nb][0];
            pp[crow * D + e0 + 1]       = c2[nb][1];
            pp[(crow + 8) * D + e0]     = c2[nb][2];
            pp[(crow + 8) * D + e0 + 1] = c2[nb][3];
        }
        #pragma unroll
        for (int off = 4; off < 32; off <<= 1) {
            #pragma unroll
            for (int j = 0; j < 4; j++) {
                colsum[j][0] += __shfl_xor_sync(0xffffffffu, colsum[j][0], off);
                colsum[j][1] += __shfl_xor_sync(0xffffffffu, colsum[j][1], off);
            }
        }
        __syncthreads();
        float* scs = (float*)satr;
        if (g == 0) {
            #pragma unroll
            for (int j = 0; j < 4; j++) {
                scs[w * 32 + 8 * j + 2 * t]     = colsum[j][0];
                scs[w * 32 + 8 * j + 2 * t + 1] = colsum[j][1];
            }
        }
        __syncthreads();
        if (tid < C32) {
            float s = 0.f;
            #pragma unroll
            for (int ww = 0; ww < 4; ww++) s += scs[ww * 32 + tid];
            g_sap[(b * NCH0 + chunk) * C32 + tid] = s;
        }
    }

    signal_done(b, tid);
}

// =====================================================================
// Lite chunk body (shared by both iterations of the merged launch)
// =====================================================================
__device__ void lite_chunk(float* sm, int blk, int last, int wtgt,
                           float* __restrict__ vis)
{
    uint32_t*       sxb0 = (uint32_t*)sm;
    uint32_t*       sxb1 = sxb0 + TT * SXBU;
    __nv_bfloat16*  satr = (__nv_bfloat16*)(sxb1 + TT * SXBU);
    uint32_t*       satu = (uint32_t*)satr;
    uint32_t*       wfT  = satu + (TT * SATR / 2);

    const int b     = blk >> 4;
    const int chunk = blk & 15;
    const int n0    = chunk * TPC1;
    const int tid   = threadIdx.x;
    const int w     = tid >> 5;
    const int lane  = tid & 31;
    const int g     = lane >> 2;
    const int t     = lane & 3;
    const int r0    = w * 16 + g;

    // wait for this batch's Wfold to be published (iter-2 region only)
    if (wtgt > 0) {
        if (tid == 0) spin_ge(g_tws + b, wtgt);
        __syncthreads();
    }

    for (int i = tid; i < C32 * 32; i += 128)
        wfT[(i >> 5) * WFU + (i & 31)] = g_wfoldu[b * 1024 + i];

    const uint32_t* gbase = g_lnx + ((size_t)b * NKV + n0) * 32;
    uint32_t sxa[2];
    sxa[0] = (uint32_t)__cvta_generic_to_shared(sxb0);
    sxa[1] = (uint32_t)__cvta_generic_to_shared(sxb1);
    const uint32_t sat_s = (uint32_t)__cvta_generic_to_shared(satr);

    const int mblk = w & 1;
    const int ncol = (w >> 1) * 32;
    const int l = lane;
    const uint32_t aAddr = sat_s +
        (uint32_t)(((l & 7) + ((l >> 4) & 1) * 8) * (SATR * 2)
                   + (16 * mblk + ((l >> 3) & 1) * 8) * 2);
    const uint32_t bOff =
        (uint32_t)((l & 15) * (SXBU * 4) + (ncol + ((l >> 4) & 1) * 8) * 2);

    #pragma unroll
    for (int k = 0; k < 4; k++) {
        int i = tid + 128 * k;
        cp_async16(sxa[0] + ((i >> 3) * SXBU + (i & 7) * 4) * 4,
                   gbase + (i >> 3) * 32 + (i & 7) * 4);
    }
    cp_commit();

    float c2[4][4];
    float colsum[4][2];
    #pragma unroll
    for (int a = 0; a < 4; a++) {
        #pragma unroll
        for (int i = 0; i < 4; i++) c2[a][i] = 0.f;
        colsum[a][0] = 0.f; colsum[a][1] = 0.f;
    }

    #pragma unroll 1
    for (int t4 = 0; t4 < NT1; t4++) {
        uint32_t* sxb = (t4 & 1) ? sxb1 : sxb0;
        const uint32_t bAddr = sxa[t4 & 1] + bOff;

        cp_wait0();
        __syncthreads();

        if (t4 + 1 < NT1) {
            const uint32_t* gn = gbase + (size_t)(t4 + 1) * (TT * 32);
            uint32_t dst = sxa[(t4 + 1) & 1];
            #pragma unroll
            for (int k = 0; k < 4; k++) {
                int i = tid + 128 * k;
                cp_async16(dst + ((i >> 3) * SXBU + (i & 7) * 4) * 4,
                           gn + (i >> 3) * 32 + (i & 7) * 4);
            }
            cp_commit();
        }

        uint32_t v0p[8], v1p[8];
        {
            const uint32_t* p0 = sxb + r0 * SXBU + t;
            const uint32_t* p1 = p0 + 8 * SXBU;
            #pragma unroll
            for (int m = 0; m < 8; m++) {
                v0p[m] = p0[4 * m];
                v1p[m] = p1[4 * m];
            }
        }

        float c1[4][4];
        #pragma unroll
        for (int j = 0; j < 4; j++)
            #pragma unroll
            for (int i = 0; i < 4; i++) c1[j][i] = 0.f;
        #pragma unroll
        for (int ks = 0; ks < 4; ks++) {
            uint32_t a0 = v0p[2 * ks],     a1 = v1p[2 * ks];
            uint32_t a2 = v0p[2 * ks + 1], a3 = v1p[2 * ks + 1];
            #pragma unroll
            for (int j = 0; j < 4; j++) {
                uint32_t b0 = wfT[(8 * j + g) * WFU + 8 * ks + t];
                uint32_t b1 = wfT[(8 * j + g) * WFU + 8 * ks + t + 4];
                mma16(c1[j], a0, a1, a2, a3, b0, b1);
            }
        }

        float m0 = -1e30f, m1 = -1e30f;
        #pragma unroll
        for (int j = 0; j < 4; j++) {
            m0 = fmaxf(m0, fmaxf(c1[j][0], c1[j][1]));
            m1 = fmaxf(m1, fmaxf(c1[j][2], c1[j][3]));
        }
        m0 = fmaxf(m0, __shfl_xor_sync(0xffffffffu, m0, 1));
        m0 = fmaxf(m0, __shfl_xor_sync(0xffffffffu, m0, 2));
        m1 = fmaxf(m1, __shfl_xor_sync(0xffffffffu, m1, 1));
        m1 = fmaxf(m1, __shfl_xor_sync(0xffffffffu, m1, 2));
        float ss0 = 0.f, ss1 = 0.f;
        #pragma unroll
        for (int j = 0; j < 4; j++) {
            c1[j][0] = __expf(c1[j][0] - m0);
            c1[j][1] = __expf(c1[j][1] - m0);
            c1[j][2] = __expf(c1[j][2] - m1);
            c1[j][3] = __expf(c1[j][3] - m1);
            ss0 += c1[j][0] + c1[j][1];
            ss1 += c1[j][2] + c1[j][3];
        }
        ss0 += __shfl_xor_sync(0xffffffffu, ss0, 1);
        ss0 += __shfl_xor_sync(0xffffffffu, ss0, 2);
        ss1 += __shfl_xor_sync(0xffffffffu, ss1, 1);
        ss1 += __shfl_xor_sync(0xffffffffu, ss1, 2);
        float inv0 = 1.f / ss0, inv1 = 1.f / ss1;

        if (last) {
            float w00 = 0.f, w01 = 0.f, w10 = 0.f, w11 = 0.f;
            #pragma unroll
            for (int j = 0; j < 4; j++) {
                w00 += c1[j][0]; w01 += c1[j][1];
                w10 += c1[j][2]; w11 += c1[j][3];
            }
            size_t nrow = (size_t)b * NKV + n0 + t4 * TT;
            *reinterpret_cast<float2*>(&vis[(nrow + r0) * NQ + 2 * t])
                = make_float2(w00 * inv0, w01 * inv0);
            *reinterpret_cast<float2*>(&vis[(nrow + r0 + 8) * NQ + 2 * t])
                = make_float2(w10 * inv1, w11 * inv1);
        }

        #pragma unroll
        for (int j = 0; j < 4; j++) {
            float a00 = fmaf(c1[j][0], inv0, EPS_A);
            float a01 = fmaf(c1[j][1], inv0, EPS_A);
            float a10 = fmaf(c1[j][2], inv1, EPS_A);
            float a11 = fmaf(c1[j][3], inv1, EPS_A);
            satu[r0 * (SATR / 2) + 4 * j + t]       = pack_bf16x2(a00, a01);
            satu[(r0 + 8) * (SATR / 2) + 4 * j + t] = pack_bf16x2(a10, a11);
            colsum[j][0] += a00 + a10;
            colsum[j][1] += a01 + a11;
        }
        __syncthreads();

        #pragma unroll
        for (int ks = 0; ks < 4; ks++) {
            uint32_t a0, a1, a2, a3, f0, f1, f2, f3;
            ldm_x4t(a0, a1, a2, a3, aAddr + ks * (16 * SATR * 2));
            ldm_x4t(f0, f1, f2, f3, bAddr + ks * (16 * SXBU * 4));
            mma16(c2[0], a0, a1, a2, a3, f0, f1);
            mma16(c2[1], a0, a1, a2, a3, f2, f3);
            ldm_x4t(f0, f1, f2, f3, bAddr + ks * (16 * SXBU * 4) + 32);
            mma16(c2[2], a0, a1, a2, a3, f0, f1);
            mma16(c2[3], a0, a1, a2, a3, f2, f3);
        }
    }

    {
        const int crow = 16 * mblk + g;
        float* pp = &g_part[(size_t)(b * NCH0 + chunk) * (C32 * D)];
        #pragma unroll
        for (int nb = 0; nb < 4; nb++) {
            int e0 = ncol + 8 * nb + 2 * t;
            pp[crow * D + e0]           = c2[nb][0];
            pp[crow * D + e0 + 1]       = c2[nb][1];
            pp[(crow + 8) * D + e0]     = c2[nb][2];
            pp[(crow + 8) * D + e0 + 1] = c2[nb][3];
        }
        #pragma unroll
        for (int off = 4; off < 32; off <<= 1) {
            #pragma unroll
            for (int j = 0; j < 4; j++) {
                colsum[j][0] += __shfl_xor_sync(0xffffffffu, colsum[j][0], off);
                colsum[j][1] += __shfl_xor_sync(0xffffffffu, colsum[j][1], off);
            }
        }
        __syncthreads();
        float* scs = (float*)satr;
        if (g == 0) {
            #pragma unroll
            for (int j = 0; j < 4; j++) {
                scs[w * 32 + 8 * j + 2 * t]     = colsum[j][0];
                scs[w * 32 + 8 * j + 2 * t + 1] = colsum[j][1];
            }
        }
        __syncthreads();
        if (tid < C32) {
            float s = 0.f;
            #pragma unroll
            for (int ww = 0; ww < 4; ww++) s += scs[ww * 32 + tid];
            g_sap[(b * NCH0 + chunk) * C32 + tid] = s;
        }
    }

    signal_done(b, tid);
}

// =====================================================================
// Merged lite kernel: iter1 chunks | iter1 tails | iter2 chunks | iter2
// tails — per-batch dependency via g_cnt / g_tws counters.
// =====================================================================
__global__ void __launch_bounds__(128, 8)
vslot_lite2(float* __restrict__ vis,
            const float* __restrict__ Wq,  const float* __restrict__ Wv,
            const float* __restrict__ b_ih, const float* __restrict__ b_hh,
            const float* __restrict__ lns_g, const float* __restrict__ lns_b,
            const float* __restrict__ lnm_g, const float* __restrict__ lnm_b,
            const float* __restrict__ W1, const float* __restrict__ b1v,
            const float* __restrict__ W2, const float* __restrict__ b2v,
            float* __restrict__ out_slots)
{
    extern __shared__ float sm[];
    const int bi = blockIdx.x;

    if (bi < NMAIN1) {
        // iteration-1 chunks (Wfold0..already published by main launch's tails
        // + launch boundary, but iter0 tails bumped g_tws to 4 — no wait needed)
        lite_chunk(sm, bi, /*last=*/0, /*wtgt=*/0, vis);
    } else if (bi < NMAIN1 + NSLOT) {
        // iteration-1 slot tails: wait all 48 cumulative chunks, publish Wfold2
        slot_tail(sm, bi - NMAIN1, /*tgt=*/NCH0 + NCH1, NCH1, /*last=*/0,
                  Wq, Wv, b_ih, b_hh, lns_g, lns_b, lnm_g, lnm_b,
                  W1, b1v, W2, b2v, out_slots);
    } else if (bi < 2 * NMAIN1 + NSLOT) {
        // iteration-2 chunks: wait for this batch's Wfold2 (g_tws >= 8)
        lite_chunk(sm, bi - (NMAIN1 + NSLOT), /*last=*/1, /*wtgt=*/8, vis);
    } else {
        // iteration-2 slot tails: final slots -> out
        slot_tail(sm, bi - (2 * NMAIN1 + NSLOT), /*tgt=*/NCH0 + 2 * NCH1, NCH1,
                  /*last=*/1, Wq, Wv, b_ih, b_hh, lns_g, lns_b, lnm_g, lnm_b,
                  W1, b1v, W2, b2v, out_slots);
    }
}

// =====================================================================
// Init kernel: reset counters, slots copy, Wfold0, weight transposes.
// =====================================================================
__global__ void __launch_bounds__(128)
vslot_init(const float* __restrict__ slots_in,
           const float* __restrict__ Wq, const float* __restrict__ Wk,
           const float* __restrict__ W_ih, const float* __restrict__ W_hh,
           const float* __restrict__ lns_g, const float* __restrict__ lns_b)
{
    __shared__ float s_s[512], s_ln[512], s_qm[512];
    const int b = blockIdx.x, tid = threadIdx.x;
    const int w = tid >> 5, lane = tid & 31;

    if (b == 0 && tid < B_) { g_cnt[tid] = 0; g_tws[tid] = 0; }

    for (int i = tid; i < 512; i += 128) {
        float v = slots_in[b * 512 + i];
        s_s[i] = v;
        g_slots[b * 512 + i] = v;
    }

    if (tid < 64) {
        #pragma unroll
        for (int j = 0; j < 3; j++) {
            int cc = 3 * b + j;
            g_wihT[tid * 192 + cc] = W_ih[cc * 64 + tid];
            g_whhT[tid * 192 + cc] = W_hh[cc * 64 + tid];
        }
        g_wkT[b * 64 + tid] = Wk[tid * 64 + b];
    }
    __syncthreads();

    #pragma unroll
    for (int rep = 0; rep < 2; rep++) {
        int q = w + 4 * rep;
        float x0 = s_s[q * 64 + lane], x1 = s_s[q * 64 + 32 + lane];
        float s = x0 + x1, qq = x0 * x0 + x1 * x1;
        #pragma unroll
        for (int off = 16; off; off >>= 1) {
            s  += __shfl_xor_sync(0xffffffffu, s,  off);
            qq += __shfl_xor_sync(0xffffffffu, qq, off);
        }
        float m = s * (1.f / 64.f);
        float rs = rsqrtf(qq * (1.f / 64.f) - m * m + 1e-5f);
        s_ln[q * 64 + lane]      = (x0 - m) * rs * lns_g[lane]      + lns_b[lane];
        s_ln[q * 64 + 32 + lane] = (x1 - m) * rs * lns_g[lane + 32] + lns_b[lane + 32];
    }
    __syncthreads();

    for (int o = tid; o < 512; o += 128) {
        int q = o >> 6, e = o & 63;
        float acc = 0.f;
        #pragma unroll
        for (int dd = 0; dd < 64; dd++)
            acc = fmaf(s_ln[q * 64 + dd], Wq[dd * 64 + e], acc);
        s_qm[o] = acc;
    }
    __syncthreads();

    for (int o = tid; o < 1024; o += 128) {
        int c = o >> 5, ep = o & 31, h = c >> 3, q = c & 7;
        float a0 = 0.f, a1 = 0.f;
        #pragma unroll
        for (int dd = 0; dd < 16; dd++) {
            float qv = s_qm[q * 64 + h * 16 + dd];
            a0 = fmaf(Wk[(2 * ep) * 64 + h * 16 + dd],     qv, a0);
            a1 = fmaf(Wk[(2 * ep + 1) * 64 + h * 16 + dd], qv, a1);
        }
        g_wfoldu[b * 1024 + c * 32 + ep] = pack_bf16x2(0.25f * a0, 0.25f * a1);
    }
}

// =====================================================================
// launcher: 3 launches
// =====================================================================
extern "C" void kernel_launch(void* const* d_in, const int* in_sizes, int n_in,
                              void* d_out, int out_size)
{
    const float* inputs = (const float*)d_in[0];
    const float* slots  = (const float*)d_in[1];
    const float* lnin_g = (const float*)d_in[2];
    const float* lnin_b = (const float*)d_in[3];
    const float* lns_g  = (const float*)d_in[4];
    const float* lns_b  = (const float*)d_in[5];
    const float* lnm_g  = (const float*)d_in[6];
    const float* lnm_b  = (const float*)d_in[7];
    const float* Wq     = (const float*)d_in[8];
    const float* Wk     = (const float*)d_in[9];
    const float* Wv     = (const float*)d_in[10];
    const float* W_ih   = (const float*)d_in[11];
    const float* W_hh   = (const float*)d_in[12];
    const float* b_ih   = (const float*)d_in[13];
    const float* b_hh   = (const float*)d_in[14];
    const float* W1     = (const float*)d_in[15];
    const float* b1     = (const float*)d_in[16];
    const float* W2     = (const float*)d_in[17];
    const float* b2     = (const float*)d_in[18];

    float* out       = (float*)d_out;
    float* out_slots = out;
    float* out_vis   = out + B_ * NQ * D;

    size_t smem = 2 * TT * SXF * 4 + TT * SXBU * 4 + TT * SATR * 2
                + C32 * WFU * 4 + 128 * 4;
    cudaFuncSetAttribute(vslot_main,
                         cudaFuncAttributeMaxDynamicSharedMemorySize, (int)smem);
    size_t smem_l = 2 * TT * SXBU * 4 + TT * SATR * 2 + C32 * WFU * 4;
    cudaFuncSetAttribute(vslot_lite2,
                         cudaFuncAttributeMaxDynamicSharedMemorySize, (int)smem_l);

    vslot_init<<<B_, 128>>>(slots, Wq, Wk, W_ih, W_hh, lns_g, lns_b);

    vslot_main<<<NMAIN0 + NSLOT, 128, smem>>>(
        inputs, lnin_g, lnin_b, /*tgt=*/NCH0,
        Wq, Wv, b_ih, b_hh, lns_g, lns_b, lnm_g, lnm_b,
        W1, b1, W2, b2, out_slots);

    vslot_lite2<<<2 * (NMAIN1 + NSLOT), 128, smem_l>>>(
        out_vis, Wq, Wv, b_ih, b_hh, lns_g, lns_b, lnm_g, lnm_b,
        W1, b1, W2, b2, out_slots);
}

// round 17
// speedup vs baseline: 1.0830x; 1.0830x over previous
#include <cuda_runtime.h>
#include <cuda_bf16.h>
#include <cstdint>
#include <cstddef>

// ---------------- problem constants ----------------
#define B_     64
#define NKV    8192
#define D      64
#define NQ     8
#define C32    32
#define EPS_A  1e-8f
#define TT     64

// pass 0 (fp32 input) config
#define NCH0   32
#define TPC0   256
#define NT0    (TPC0 / TT)      // 4
#define NMAIN0 (B_ * NCH0)      // 2048

// pass 1,2 (cached bf16) config
#define NCH1   16
#define TPC1   512
#define NT1    (TPC1 / TT)      // 8
#define NMAIN1 (B_ * NCH1)      // 1024

#define NSLOT  (B_ * 4)         // 256 slot CTAs (4 per batch, 2 slots each)

#define SXF 68
#define SXBU 36
#define SATR 40
#define WFU 36

// ---------------- device scratch ----------------
__device__ uint32_t g_wfoldu[B_ * C32 * 32];          // bf16x2 Wfold
__device__ uint32_t g_lnx  [B_ * NKV * 32];           // bf16x2 lnX cache
__device__ float    g_part [B_ * NCH0 * C32 * D];     // per-chunk S' partials
__device__ float    g_sap  [B_ * NCH0 * C32];         // per-chunk colsum partials
__device__ float    g_slots[B_ * NQ * D];             // working slots
__device__ int      g_cnt  [B_];                      // arrival counters (cumulative)
__device__ float    g_wihT [64 * 192];                // W_ih^T
__device__ float    g_whhT [64 * 192];                // W_hh^T
__device__ float    g_wkT  [64 * 64];                 // Wk^T

// ---------------- helpers ----------------
__device__ __forceinline__ uint32_t pack_bf16x2(float lo, float hi) {
    uint32_t r;
    asm("cvt.rn.bf16x2.f32 %0, %1, %2;" : "=r"(r) : "f"(hi), "f"(lo));
    return r;
}
__device__ __forceinline__ void mma16(float c[4],
                                      uint32_t a0, uint32_t a1, uint32_t a2, uint32_t a3,
                                      uint32_t b0, uint32_t b1) {
    asm volatile(
        "mma.sync.aligned.m16n8k16.row.col.f32.bf16.bf16.f32 "
        "{%0,%1,%2,%3},{%4,%5,%6,%7},{%8,%9},{%0,%1,%2,%3};"
        : "+f"(c[0]), "+f"(c[1]), "+f"(c[2]), "+f"(c[3])
        : "r"(a0), "r"(a1), "r"(a2), "r"(a3), "r"(b0), "r"(b1));
}
__device__ __forceinline__ void ldm_x4t(uint32_t& r0, uint32_t& r1, uint32_t& r2, uint32_t& r3,
                                        uint32_t addr) {
    asm volatile("ldmatrix.sync.aligned.m8n8.x4.trans.shared.b16 {%0,%1,%2,%3}, [%4];"
                 : "=r"(r0), "=r"(r1), "=r"(r2), "=r"(r3) : "r"(addr));
}
__device__ __forceinline__ void cp_async16(uint32_t smem_addr, const void* gptr) {
    asm volatile("cp.async.cg.shared.global [%0], [%1], 16;"
                 :: "r"(smem_addr), "l"(gptr));
}
__device__ __forceinline__ void cp_commit() { asm volatile("cp.async.commit_group;"); }
__device__ __forceinline__ void cp_wait0()  { asm volatile("cp.async.wait_group 0;"); }
__device__ __forceinline__ float sigm(float x) { return 1.f / (1.f + __expf(-x)); }

__device__ __forceinline__ void spin_ge(const int* addr, int tgt) {
    int v = 0;
    while (v < tgt) {
        asm volatile("ld.acquire.gpu.global.s32 %0, [%1];" : "=r"(v) : "l"(addr));
        if (v < tgt) __nanosleep(200);
    }
}

__device__ __forceinline__ void signal_done(int b, int tid) {
    __threadfence();
    __syncthreads();
    if (tid == 0) atomicAdd(&g_cnt[b], 1);
}

// =====================================================================
// Slot-update tail: 4 CTAs per batch (2 slots each), 128 threads.
// =====================================================================
__device__ void slot_tail(float* S, int sb, int tgt, int nch, int last,
                          const float* __restrict__ Wq,
                          const float* __restrict__ Wv,
                          const float* __restrict__ b_ih, const float* __restrict__ b_hh,
                          const float* __restrict__ lns_g, const float* __restrict__ lns_b,
                          const float* __restrict__ lnm_g, const float* __restrict__ lnm_b,
                          const float* __restrict__ W1, const float* __restrict__ b1v,
                          const float* __restrict__ W2, const float* __restrict__ b2v,
                          float* __restrict__ out_slots)
{
    const int b = sb >> 2;
    const int p = sb & 3;            // slot pair: q in {2p, 2p+1}
    const int tid = threadIdx.x;
    const int w = tid >> 5, lane = tid & 31;

    float* s_sax = S;                // [8][64]
    float* s_sa  = S + 512;          // [8]
    float* s_sl  = S + 520;          // [2][64]
    float* s_up  = S + 648;          // [2][64]
    float* s_gx  = S + 776;          // [2][192]
    float* s_gh  = S + 1160;         // [2][192]
    float* s_ln  = S + 1544;         // [2][64]
    float* s_hid = S + 1672;         // [2][128]

    if (tid == 0) spin_ge(g_cnt + b, tgt);
    __syncthreads();

    #pragma unroll
    for (int k = 0; k < 4; k++) {
        int o = tid + 128 * k;
        int lr = o >> 6, e = o & 63;
        int h = lr >> 1, q = 2 * p + (lr & 1);
        int c = h * 8 + q;
        const float* gp = g_part + ((size_t)b * NCH0 * C32 + c) * D + e;
        float a0 = 0.f, a1 = 0.f;
        for (int ch = 0; ch < nch; ch += 2) {
            a0 += gp[(size_t)ch * (C32 * D)];
            a1 += gp[(size_t)(ch + 1) * (C32 * D)];
        }
        s_sax[lr * 64 + e] = a0 + a1;
    }
    if (tid < 8) {
        int h = tid >> 1, q = 2 * p + (tid & 1);
        int c = h * 8 + q;
        float s = 0.f;
        for (int ch = 0; ch < nch; ch++)
            s += g_sap[(b * NCH0 + ch) * C32 + c];
        s_sa[tid] = s;
    }
    {
        int qi = tid >> 6, dd = tid & 63;
        s_sl[qi * 64 + dd] = g_slots[(b * NQ + 2 * p + qi) * 64 + dd];
    }
    __syncthreads();

    {
        int qi = tid >> 6, hd = tid & 63, h = hd >> 4;
        const float* sr = s_sax + (h * 2 + qi) * 64;
        float a0 = 0.f, a1 = 0.f;
        #pragma unroll
        for (int e = 0; e < 64; e += 2) {
            a0 = fmaf(sr[e],     Wv[e * 64 + hd],       a0);
            a1 = fmaf(sr[e + 1], Wv[(e + 1) * 64 + hd], a1);
        }
        s_up[qi * 64 + hd] = (a0 + a1) / s_sa[h * 2 + qi];
    }
    __syncthreads();

    #pragma unroll
    for (int k = 0; k < 3; k++) {
        int o = tid + 128 * k;
        int qi = (o >= 192) ? 1 : 0;
        int cc = o - 192 * qi;
        const float* xu = s_up + qi * 64;
        const float* xs = s_sl + qi * 64;
        float gx0 = 0.f, gx1 = 0.f, gh0 = 0.f, gh1 = 0.f;
        #pragma unroll 8
        for (int dd = 0; dd < 64; dd += 2) {
            gx0 = fmaf(xu[dd],     g_wihT[dd * 192 + cc],       gx0);
            gx1 = fmaf(xu[dd + 1], g_wihT[(dd + 1) * 192 + cc], gx1);
            gh0 = fmaf(xs[dd],     g_whhT[dd * 192 + cc],       gh0);
            gh1 = fmaf(xs[dd + 1], g_whhT[(dd + 1) * 192 + cc], gh1);
        }
        s_gx[qi * 192 + cc] = gx0 + gx1 + b_ih[cc];
        s_gh[qi * 192 + cc] = gh0 + gh1 + b_hh[cc];
    }
    __syncthreads();

    {
        int qi = tid >> 6, dd = tid & 63;
        float r = sigm(s_gx[qi * 192 + dd]        + s_gh[qi * 192 + dd]);
        float z = sigm(s_gx[qi * 192 + 64 + dd]   + s_gh[qi * 192 + 64 + dd]);
        float n = tanhf(s_gx[qi * 192 + 128 + dd] + r * s_gh[qi * 192 + 128 + dd]);
        s_up[qi * 64 + dd] = (1.f - z) * n + z * s_sl[qi * 64 + dd];
    }
    __syncthreads();

    if (w < 2) {
        float x0 = s_up[w * 64 + lane], x1 = s_up[w * 64 + 32 + lane];
        float s = x0 + x1, qq = x0 * x0 + x1 * x1;
        #pragma unroll
        for (int off = 16; off; off >>= 1) {
            s  += __shfl_xor_sync(0xffffffffu, s,  off);
            qq += __shfl_xor_sync(0xffffffffu, qq, off);
        }
        float m = s * (1.f / 64.f);
        float rs = rsqrtf(qq * (1.f / 64.f) - m * m + 1e-5f);
        s_ln[w * 64 + lane]      = (x0 - m) * rs * lnm_g[lane]      + lnm_b[lane];
        s_ln[w * 64 + 32 + lane] = (x1 - m) * rs * lnm_g[lane + 32] + lnm_b[lane + 32];
    }
    __syncthreads();

    #pragma unroll
    for (int k = 0; k < 2; k++) {
        int o = tid + 128 * k;
        int qi = o >> 7, j = o & 127;
        const float* xl = s_ln + qi * 64;
        float a0 = 0.f, a1 = 0.f;
        #pragma unroll 8
        for (int dd = 0; dd < 64; dd += 2) {
            a0 = fmaf(xl[dd],     W1[dd * 128 + j],       a0);
            a1 = fmaf(xl[dd + 1], W1[(dd + 1) * 128 + j], a1);
        }
        s_hid[qi * 128 + j] = fmaxf(a0 + a1 + b1v[j], 0.f);
    }
    __syncthreads();

    {
        int qi = tid >> 6, dd = tid & 63;
        const float* hh = s_hid + qi * 128;
        float a0 = 0.f, a1 = 0.f;
        #pragma unroll 8
        for (int j = 0; j < 128; j += 2) {
            a0 = fmaf(hh[j],     W2[j * 64 + dd],       a0);
            a1 = fmaf(hh[j + 1], W2[(j + 1) * 64 + dd], a1);
        }
        float fin = s_up[qi * 64 + dd] + a0 + a1 + b2v[dd];
        s_sl[qi * 64 + dd] = fin;
        g_slots[(b * NQ + 2 * p + qi) * 64 + dd] = fin;
        if (last) out_slots[(b * NQ + 2 * p + qi) * 64 + dd] = fin;
    }
    __syncthreads();
    if (last) return;

    if (w < 2) {
        float x0 = s_sl[w * 64 + lane], x1 = s_sl[w * 64 + 32 + lane];
        float s = x0 + x1, qq = x0 * x0 + x1 * x1;
        #pragma unroll
        for (int off = 16; off; off >>= 1) {
            s  += __shfl_xor_sync(0xffffffffu, s,  off);
            qq += __shfl_xor_sync(0xffffffffu, qq, off);
        }
        float m = s * (1.f / 64.f);
        float rs = rsqrtf(qq * (1.f / 64.f) - m * m + 1e-5f);
        s_ln[w * 64 + lane]      = (x0 - m) * rs * lns_g[lane]      + lns_b[lane];
        s_ln[w * 64 + 32 + lane] = (x1 - m) * rs * lns_g[lane + 32] + lns_b[lane + 32];
    }
    __syncthreads();

    {
        int qi = tid >> 6, e = tid & 63;
        const float* xl = s_ln + qi * 64;
        float a0 = 0.f, a1 = 0.f;
        #pragma unroll 8
        for (int dd = 0; dd < 64; dd += 2) {
            a0 = fmaf(xl[dd],     Wq[dd * 64 + e],       a0);
            a1 = fmaf(xl[dd + 1], Wq[(dd + 1) * 64 + e], a1);
        }
        s_hid[qi * 64 + e] = a0 + a1;
    }
    __syncthreads();

    #pragma unroll
    for (int k = 0; k < 2; k++) {
        int o = tid + 128 * k;
        int lr = o >> 5, ep = o & 31;
        int h = lr >> 1, qi = lr & 1, q = 2 * p + qi, c = h * 8 + q;
        float a0 = 0.f, a1 = 0.f;
        #pragma unroll
        for (int dd = 0; dd < 16; dd++) {
            float qv = s_hid[qi * 64 + h * 16 + dd];
            float2 wk = ((const float2*)(g_wkT + (h * 16 + dd) * 64))[ep];
            a0 = fmaf(wk.x, qv, a0);
            a1 = fmaf(wk.y, qv, a1);
        }
        g_wfoldu[b * 1024 + c * 32 + ep] = pack_bf16x2(0.25f * a0, 0.25f * a1);
    }
}

// =====================================================================
// Pass-0 fused kernel (R14-proven): 32 chunks x 256 tokens + slot CTAs
// =====================================================================
__global__ void __launch_bounds__(128, 4)
vslot_main(const float* __restrict__ inputs,
           const float* __restrict__ lng_g,
           const float* __restrict__ lnb_g,
           int tgt,
           const float* __restrict__ Wq,  const float* __restrict__ Wv,
           const float* __restrict__ b_ih, const float* __restrict__ b_hh,
           const float* __restrict__ lns_g, const float* __restrict__ lns_b,
           const float* __restrict__ lnm_g, const float* __restrict__ lnm_b,
           const float* __restrict__ W1, const float* __restrict__ b1v,
           const float* __restrict__ W2, const float* __restrict__ b2v,
           float* __restrict__ out_slots)
{
    extern __shared__ float sm[];

    if (blockIdx.x >= NMAIN0) {
        slot_tail(sm, blockIdx.x - NMAIN0, tgt, NCH0, 0, Wq, Wv, b_ih, b_hh,
                  lns_g, lns_b, lnm_g, lnm_b, W1, b1v, W2, b2v, out_slots);
        return;
    }

    float*          sxf0 = sm;
    float*          sxf1 = sxf0 + TT * SXF;
    uint32_t*       sxb  = (uint32_t*)(sxf1 + TT * SXF);
    __nv_bfloat16*  satr = (__nv_bfloat16*)(sxb + TT * SXBU);
    uint32_t*       satu = (uint32_t*)satr;
    uint32_t*       wfT  = satu + (TT * SATR / 2);
    float*          slng = (float*)(wfT + C32 * WFU);
    float*          slnb = slng + 64;

    const int b     = blockIdx.x >> 5;
    const int chunk = blockIdx.x & 31;
    const int n0    = chunk * TPC0;
    const int tid   = threadIdx.x;
    const int w     = tid >> 5;
    const int lane  = tid & 31;
    const int g     = lane >> 2;
    const int t     = lane & 3;
    const int r0    = w * 16 + g;

    for (int i = tid; i < C32 * 32; i += 128)
        wfT[(i >> 5) * WFU + (i & 31)] = g_wfoldu[b * 1024 + i];
    if (tid < 64) { slng[tid] = lng_g[tid]; slnb[tid] = lnb_g[tid]; }

    const float4* gbase = reinterpret_cast<const float4*>(
        inputs + ((size_t)b * NKV + n0) * D);
    uint32_t sxa[2];
    sxa[0] = (uint32_t)__cvta_generic_to_shared(sxf0);
    sxa[1] = (uint32_t)__cvta_generic_to_shared(sxf1);
    const uint32_t sat_s = (uint32_t)__cvta_generic_to_shared(satr);
    const uint32_t sxb_s = (uint32_t)__cvta_generic_to_shared(sxb);

    const int mblk = w & 1;
    const int ncol = (w >> 1) * 32;
    const int l = lane;
    const uint32_t aAddr = sat_s +
        (uint32_t)(((l & 7) + ((l >> 4) & 1) * 8) * (SATR * 2)
                   + (16 * mblk + ((l >> 3) & 1) * 8) * 2);
    const uint32_t bAddr = sxb_s +
        (uint32_t)((l & 15) * (SXBU * 4) + (ncol + ((l >> 4) & 1) * 8) * 2);

    #pragma unroll
    for (int k = 0; k < 8; k++) {
        int i = tid + 128 * k;
        cp_async16(sxa[0] + ((i >> 4) * SXF + (i & 15) * 4) * 4, gbase + i);
    }
    cp_commit();

    float c2[4][4];
    float colsum[4][2];
    #pragma unroll
    for (int a = 0; a < 4; a++) {
        #pragma unroll
        for (int i = 0; i < 4; i++) c2[a][i] = 0.f;
        colsum[a][0] = 0.f; colsum[a][1] = 0.f;
    }

    #pragma unroll
    for (int t4 = 0; t4 < NT0; t4++) {
        const float* sxf = (t4 & 1) ? sxf1 : sxf0;

        cp_wait0();
        __syncthreads();

        if (t4 + 1 < NT0) {
            const float4* gn = gbase + (size_t)(t4 + 1) * (TT * D / 4);
            uint32_t dst = sxa[(t4 + 1) & 1];
            #pragma unroll
            for (int k = 0; k < 8; k++) {
                int i = tid + 128 * k;
                cp_async16(dst + ((i >> 4) * SXF + (i & 15) * 4) * 4, gn + i);
            }
            cp_commit();
        }

        // ---- layernorm ----
        float2 x0[8], x1[8];
        float s0 = 0.f, q0 = 0.f, s1 = 0.f, q1 = 0.f;
        {
            const float* p0 = sxf + r0 * SXF + 2 * t;
            const float* p1 = p0 + 8 * SXF;
            #pragma unroll
            for (int m = 0; m < 8; m++) {
                x0[m] = *reinterpret_cast<const float2*>(p0 + 8 * m);
                x1[m] = *reinterpret_cast<const float2*>(p1 + 8 * m);
                s0 += x0[m].x + x0[m].y;
                q0 = fmaf(x0[m].x, x0[m].x, fmaf(x0[m].y, x0[m].y, q0));
                s1 += x1[m].x + x1[m].y;
                q1 = fmaf(x1[m].x, x1[m].x, fmaf(x1[m].y, x1[m].y, q1));
            }
        }
        s0 += __shfl_xor_sync(0xffffffffu, s0, 1);
        q0 += __shfl_xor_sync(0xffffffffu, q0, 1);
        s1 += __shfl_xor_sync(0xffffffffu, s1, 1);
        q1 += __shfl_xor_sync(0xffffffffu, q1, 1);
        s0 += __shfl_xor_sync(0xffffffffu, s0, 2);
        q0 += __shfl_xor_sync(0xffffffffu, q0, 2);
        s1 += __shfl_xor_sync(0xffffffffu, s1, 2);
        q1 += __shfl_xor_sync(0xffffffffu, q1, 2);
        float mu0 = s0 * (1.f / 64.f), mu1 = s1 * (1.f / 64.f);
        float rs0 = rsqrtf(fmaf(-mu0, mu0, q0 * (1.f / 64.f)) + 1e-5f);
        float rs1 = rsqrtf(fmaf(-mu1, mu1, q1 * (1.f / 64.f)) + 1e-5f);

        uint32_t v0p[8], v1p[8];
        {
            uint32_t* o0 = sxb + r0 * SXBU + t;
            uint32_t* o1 = o0 + 8 * SXBU;
            #pragma unroll
            for (int m = 0; m < 8; m++) {
                float2 gb = *reinterpret_cast<const float2*>(slng + 2 * t + 8 * m);
                float2 bb = *reinterpret_cast<const float2*>(slnb + 2 * t + 8 * m);
                float y00 = fmaf((x0[m].x - mu0) * rs0, gb.x, bb.x);
                float y01 = fmaf((x0[m].y - mu0) * rs0, gb.y, bb.y);
                float y10 = fmaf((x1[m].x - mu1) * rs1, gb.x, bb.x);
                float y11 = fmaf((x1[m].y - mu1) * rs1, gb.y, bb.y);
                v0p[m] = pack_bf16x2(y00, y01);
                v1p[m] = pack_bf16x2(y10, y11);
                o0[4 * m] = v0p[m];
                o1[4 * m] = v1p[m];
            }
        }

        // ---- GEMM1 ----
        float c1[4][4];
        #pragma unroll
        for (int j = 0; j < 4; j++)
            #pragma unroll
            for (int i = 0; i < 4; i++) c1[j][i] = 0.f;
        #pragma unroll
        for (int ks = 0; ks < 4; ks++) {
            uint32_t a0 = v0p[2 * ks],     a1 = v1p[2 * ks];
            uint32_t a2 = v0p[2 * ks + 1], a3 = v1p[2 * ks + 1];
            #pragma unroll
            for (int j = 0; j < 4; j++) {
                uint32_t b0 = wfT[(8 * j + g) * WFU + 8 * ks + t];
                uint32_t b1 = wfT[(8 * j + g) * WFU + 8 * ks + t + 4];
                mma16(c1[j], a0, a1, a2, a3, b0, b1);
            }
        }

        // ---- softmax ----
        float m0 = -1e30f, m1 = -1e30f;
        #pragma unroll
        for (int j = 0; j < 4; j++) {
            m0 = fmaxf(m0, fmaxf(c1[j][0], c1[j][1]));
            m1 = fmaxf(m1, fmaxf(c1[j][2], c1[j][3]));
        }
        m0 = fmaxf(m0, __shfl_xor_sync(0xffffffffu, m0, 1));
        m0 = fmaxf(m0, __shfl_xor_sync(0xffffffffu, m0, 2));
        m1 = fmaxf(m1, __shfl_xor_sync(0xffffffffu, m1, 1));
        m1 = fmaxf(m1, __shfl_xor_sync(0xffffffffu, m1, 2));
        float ss0 = 0.f, ss1 = 0.f;
        #pragma unroll
        for (int j = 0; j < 4; j++) {
            c1[j][0] = __expf(c1[j][0] - m0);
            c1[j][1] = __expf(c1[j][1] - m0);
            c1[j][2] = __expf(c1[j][2] - m1);
            c1[j][3] = __expf(c1[j][3] - m1);
            ss0 += c1[j][0] + c1[j][1];
            ss1 += c1[j][2] + c1[j][3];
        }
        ss0 += __shfl_xor_sync(0xffffffffu, ss0, 1);
        ss0 += __shfl_xor_sync(0xffffffffu, ss0, 2);
        ss1 += __shfl_xor_sync(0xffffffffu, ss1, 1);
        ss1 += __shfl_xor_sync(0xffffffffu, ss1, 2);
        float inv0 = 1.f / ss0, inv1 = 1.f / ss1;

        // ---- attn+eps -> satr + colsums ----
        #pragma unroll
        for (int j = 0; j < 4; j++) {
            float a00 = fmaf(c1[j][0], inv0, EPS_A);
            float a01 = fmaf(c1[j][1], inv0, EPS_A);
            float a10 = fmaf(c1[j][2], inv1, EPS_A);
            float a11 = fmaf(c1[j][3], inv1, EPS_A);
            satu[r0 * (SATR / 2) + 4 * j + t]       = pack_bf16x2(a00, a01);
            satu[(r0 + 8) * (SATR / 2) + 4 * j + t] = pack_bf16x2(a10, a11);
            colsum[j][0] += a00 + a10;
            colsum[j][1] += a01 + a11;
        }
        __syncthreads();

        // ---- GEMM2 ----
        #pragma unroll
        for (int ks = 0; ks < 4; ks++) {
            uint32_t a0, a1, a2, a3, f0, f1, f2, f3;
            ldm_x4t(a0, a1, a2, a3, aAddr + ks * (16 * SATR * 2));
            ldm_x4t(f0, f1, f2, f3, bAddr + ks * (16 * SXBU * 4));
            mma16(c2[0], a0, a1, a2, a3, f0, f1);
            mma16(c2[1], a0, a1, a2, a3, f2, f3);
            ldm_x4t(f0, f1, f2, f3, bAddr + ks * (16 * SXBU * 4) + 32);
            mma16(c2[2], a0, a1, a2, a3, f0, f1);
            mma16(c2[3], a0, a1, a2, a3, f2, f3);
        }

        // ---- dump bf16 lnX tile to cache ----
        {
            uint32_t* gl = g_lnx + ((size_t)b * NKV + n0 + t4 * TT) * 32;
            #pragma unroll
            for (int k = 0; k < 16; k++) {
                int i = tid + 128 * k;
                gl[i] = sxb[(i >> 5) * SXBU + (i & 31)];
            }
        }
    }

    // ---- epilogue ----
    {
        const int crow = 16 * mblk + g;
        float* pp = &g_part[(size_t)(b * NCH0 + chunk) * (C32 * D)];
        #pragma unroll
        for (int nb = 0; nb < 4; nb++) {
            int e0 = ncol + 8 * nb + 2 * t;
            pp[crow * D + e0]           = c2[nb][0];
            pp[crow * D + e0 + 1]       = c2[nb][1];
            pp[(crow + 8) * D + e0]     = c2[nb][2];
            pp[(crow + 8) * D + e0 + 1] = c2[nb][3];
        }
        #pragma unroll
        for (int off = 4; off < 32; off <<= 1) {
            #pragma unroll
            for (int j = 0; j < 4; j++) {
                colsum[j][0] += __shfl_xor_sync(0xffffffffu, colsum[j][0], off);
                colsum[j][1] += __shfl_xor_sync(0xffffffffu, colsum[j][1], off);
            }
        }
        __syncthreads();
        float* scs = (float*)satr;
        if (g == 0) {
            #pragma unroll
            for (int j = 0; j < 4; j++) {
                scs[w * 32 + 8 * j + 2 * t]     = colsum[j][0];
                scs[w * 32 + 8 * j + 2 * t + 1] = colsum[j][1];
            }
        }
        __syncthreads();
        if (tid < C32) {
            float s = 0.f;
            #pragma unroll
            for (int ww = 0; ww < 4; ww++) s += scs[ww * 32 + tid];
            g_sap[(b * NCH0 + chunk) * C32 + tid] = s;
        }
    }

    signal_done(b, tid);
}

// =====================================================================
// Lite fused kernel (16 chunks x 512 tokens, occ 8) + slot CTAs
// =====================================================================
__global__ void __launch_bounds__(128, 8)
vslot_lite(float* __restrict__ vis, int last, int tgt,
           const float* __restrict__ Wq,  const float* __restrict__ Wv,
           const float* __restrict__ b_ih, const float* __restrict__ b_hh,
           const float* __restrict__ lns_g, const float* __restrict__ lns_b,
           const float* __restrict__ lnm_g, const float* __restrict__ lnm_b,
           const float* __restrict__ W1, const float* __restrict__ b1v,
           const float* __restrict__ W2, const float* __restrict__ b2v,
           float* __restrict__ out_slots)
{
    extern __shared__ float sm[];

    if (blockIdx.x >= NMAIN1) {
        slot_tail(sm, blockIdx.x - NMAIN1, tgt, NCH1, last, Wq, Wv, b_ih, b_hh,
                  lns_g, lns_b, lnm_g, lnm_b, W1, b1v, W2, b2v, out_slots);
        return;
    }

    uint32_t*       sxb0 = (uint32_t*)sm;
    uint32_t*       sxb1 = sxb0 + TT * SXBU;
    __nv_bfloat16*  satr = (__nv_bfloat16*)(sxb1 + TT * SXBU);
    uint32_t*       satu = (uint32_t*)satr;
    uint32_t*       wfT  = satu + (TT * SATR / 2);

    const int b     = blockIdx.x >> 4;
    const int chunk = blockIdx.x & 15;
    const int n0    = chunk * TPC1;
    const int tid   = threadIdx.x;
    const int w     = tid >> 5;
    const int lane  = tid & 31;
    const int g     = lane >> 2;
    const int t     = lane & 3;
    const int r0    = w * 16 + g;

    for (int i = tid; i < C32 * 32; i += 128)
        wfT[(i >> 5) * WFU + (i & 31)] = g_wfoldu[b * 1024 + i];

    const uint32_t* gbase = g_lnx + ((size_t)b * NKV + n0) * 32;
    uint32_t sxa[2];
    sxa[0] = (uint32_t)__cvta_generic_to_shared(sxb0);
    sxa[1] = (uint32_t)__cvta_generic_to_shared(sxb1);
    const uint32_t sat_s = (uint32_t)__cvta_generic_to_shared(satr);

    const int mblk = w & 1;
    const int ncol = (w >> 1) * 32;
    const int l = lane;
    const uint32_t aAddr = sat_s +
        (uint32_t)(((l & 7) + ((l >> 4) & 1) * 8) * (SATR * 2)
                   + (16 * mblk + ((l >> 3) & 1) * 8) * 2);
    const uint32_t bOff =
        (uint32_t)((l & 15) * (SXBU * 4) + (ncol + ((l >> 4) & 1) * 8) * 2);

    #pragma unroll
    for (int k = 0; k < 4; k++) {
        int i = tid + 128 * k;
        cp_async16(sxa[0] + ((i >> 3) * SXBU + (i & 7) * 4) * 4,
                   gbase + (i >> 3) * 32 + (i & 7) * 4);
    }
    cp_commit();

    float c2[4][4];
    float colsum[4][2];
    #pragma unroll
    for (int a = 0; a < 4; a++) {
        #pragma unroll
        for (int i = 0; i < 4; i++) c2[a][i] = 0.f;
        colsum[a][0] = 0.f; colsum[a][1] = 0.f;
    }

    #pragma unroll 1
    for (int t4 = 0; t4 < NT1; t4++) {
        uint32_t* sxb = (t4 & 1) ? sxb1 : sxb0;
        const uint32_t bAddr = sxa[t4 & 1] + bOff;

        cp_wait0();
        __syncthreads();

        if (t4 + 1 < NT1) {
            const uint32_t* gn = gbase + (size_t)(t4 + 1) * (TT * 32);
            uint32_t dst = sxa[(t4 + 1) & 1];
            #pragma unroll
            for (int k = 0; k < 4; k++) {
                int i = tid + 128 * k;
                cp_async16(dst + ((i >> 3) * SXBU + (i & 7) * 4) * 4,
                           gn + (i >> 3) * 32 + (i & 7) * 4);
            }
            cp_commit();
        }

        uint32_t v0p[8], v1p[8];
        {
            const uint32_t* p0 = sxb + r0 * SXBU + t;
            const uint32_t* p1 = p0 + 8 * SXBU;
            #pragma unroll
            for (int m = 0; m < 8; m++) {
                v0p[m] = p0[4 * m];
                v1p[m] = p1[4 * m];
            }
        }

        float c1[4][4];
        #pragma unroll
        for (int j = 0; j < 4; j++)
            #pragma unroll
            for (int i = 0; i < 4; i++) c1[j][i] = 0.f;
        #pragma unroll
        for (int ks = 0; ks < 4; ks++) {
            uint32_t a0 = v0p[2 * ks],     a1 = v1p[2 * ks];
            uint32_t a2 = v0p[2 * ks + 1], a3 = v1p[2 * ks + 1];
            #pragma unroll
            for (int j = 0; j < 4; j++) {
                uint32_t b0 = wfT[(8 * j + g) * WFU + 8 * ks + t];
                uint32_t b1 = wfT[(8 * j + g) * WFU + 8 * ks + t + 4];
                mma16(c1[j], a0, a1, a2, a3, b0, b1);
            }
        }

        float m0 = -1e30f, m1 = -1e30f;
        #pragma unroll
        for (int j = 0; j < 4; j++) {
            m0 = fmaxf(m0, fmaxf(c1[j][0], c1[j][1]));
            m1 = fmaxf(m1, fmaxf(c1[j][2], c1[j][3]));
        }
        m0 = fmaxf(m0, __shfl_xor_sync(0xffffffffu, m0, 1));
        m0 = fmaxf(m0, __shfl_xor_sync(0xffffffffu, m0, 2));
        m1 = fmaxf(m1, __shfl_xor_sync(0xffffffffu, m1, 1));
        m1 = fmaxf(m1, __shfl_xor_sync(0xffffffffu, m1, 2));
        float ss0 = 0.f, ss1 = 0.f;
        #pragma unroll
        for (int j = 0; j < 4; j++) {
            c1[j][0] = __expf(c1[j][0] - m0);
            c1[j][1] = __expf(c1[j][1] - m0);
            c1[j][2] = __expf(c1[j][2] - m1);
            c1[j][3] = __expf(c1[j][3] - m1);
            ss0 += c1[j][0] + c1[j][1];
            ss1 += c1[j][2] + c1[j][3];
        }
        ss0 += __shfl_xor_sync(0xffffffffu, ss0, 1);
        ss0 += __shfl_xor_sync(0xffffffffu, ss0, 2);
        ss1 += __shfl_xor_sync(0xffffffffu, ss1, 1);
        ss1 += __shfl_xor_sync(0xffffffffu, ss1, 2);
        float inv0 = 1.f / ss0, inv1 = 1.f / ss1;

        if (last) {
            float w00 = 0.f, w01 = 0.f, w10 = 0.f, w11 = 0.f;
            #pragma unroll
            for (int j = 0; j < 4; j++) {
                w00 += c1[j][0]; w01 += c1[j][1];
                w10 += c1[j][2]; w11 += c1[j][3];
            }
            size_t nrow = (size_t)b * NKV + n0 + t4 * TT;
            *reinterpret_cast<float2*>(&vis[(nrow + r0) * NQ + 2 * t])
                = make_float2(w00 * inv0, w01 * inv0);
            *reinterpret_cast<float2*>(&vis[(nrow + r0 + 8) * NQ + 2 * t])
                = make_float2(w10 * inv1, w11 * inv1);
        }

        #pragma unroll
        for (int j = 0; j < 4; j++) {
            float a00 = fmaf(c1[j][0], inv0, EPS_A);
            float a01 = fmaf(c1[j][1], inv0, EPS_A);
            float a10 = fmaf(c1[j][2], inv1, EPS_A);
            float a11 = fmaf(c1[j][3], inv1, EPS_A);
            satu[r0 * (SATR / 2) + 4 * j + t]       = pack_bf16x2(a00, a01);
            satu[(r0 + 8) * (SATR / 2) + 4 * j + t] = pack_bf16x2(a10, a11);
            colsum[j][0] += a00 + a10;
            colsum[j][1] += a01 + a11;
        }
        __syncthreads();

        #pragma unroll
        for (int ks = 0; ks < 4; ks++) {
            uint32_t a0, a1, a2, a3, f0, f1, f2, f3;
            ldm_x4t(a0, a1, a2, a3, aAddr + ks * (16 * SATR * 2));
            ldm_x4t(f0, f1, f2, f3, bAddr + ks * (16 * SXBU * 4));
            mma16(c2[0], a0, a1, a2, a3, f0, f1);
            mma16(c2[1], a0, a1, a2, a3, f2, f3);
            ldm_x4t(f0, f1, f2, f3, bAddr + ks * (16 * SXBU * 4) + 32);
            mma16(c2[2], a0, a1, a2, a3, f0, f1);
            mma16(c2[3], a0, a1, a2, a3, f2, f3);
        }
    }

    {
        const int crow = 16 * mblk + g;
        float* pp = &g_part[(size_t)(b * NCH0 + chunk) * (C32 * D)];
        #pragma unroll
        for (int nb = 0; nb < 4; nb++) {
            int e0 = ncol + 8 * nb + 2 * t;
            pp[crow * D + e0]           = c2[nb][0];
            pp[crow * D + e0 + 1]       = c2[nb][1];
            pp[(crow + 8) * D + e0]     = c2[nb][2];
            pp[(crow + 8) * D + e0 + 1] = c2[nb][3];
        }
        #pragma unroll
        for (int off = 4; off < 32; off <<= 1) {
            #pragma unroll
            for (int j = 0; j < 4; j++) {
                colsum[j][0] += __shfl_xor_sync(0xffffffffu, colsum[j][0], off);
                colsum[j][1] += __shfl_xor_sync(0xffffffffu, colsum[j][1], off);
            }
        }
        __syncthreads();
        float* scs = (float*)satr;
        if (g == 0) {
            #pragma unroll
            for (int j = 0; j < 4; j++) {
                scs[w * 32 + 8 * j + 2 * t]     = colsum[j][0];
                scs[w * 32 + 8 * j + 2 * t + 1] = colsum[j][1];
            }
        }
        __syncthreads();
        if (tid < C32) {
            float s = 0.f;
            #pragma unroll
            for (int ww = 0; ww < 4; ww++) s += scs[ww * 32 + tid];
            g_sap[(b * NCH0 + chunk) * C32 + tid] = s;
        }
    }

    signal_done(b, tid);
}

// =====================================================================
// Init kernel, PARALLELIZED: 256 CTAs (one per batch x slot-pair).
// Weight transposes distributed across CTAs. Wfold0 math identical
// per output element to the previous version (uses Wk directly).
// =====================================================================
__global__ void __launch_bounds__(128)
vslot_init(const float* __restrict__ slots_in,
           const float* __restrict__ Wq, const float* __restrict__ Wk,
           const float* __restrict__ W_ih, const float* __restrict__ W_hh,
           const float* __restrict__ lns_g, const float* __restrict__ lns_b)
{
    __shared__ float s_sl[128], s_ln[128], s_qm[128];
    const int sb  = blockIdx.x;      // 0..255
    const int b   = sb >> 2;
    const int p   = sb & 3;          // slots 2p, 2p+1
    const int tid = threadIdx.x;
    const int w   = tid >> 5, lane = tid & 31;

    if (sb == 0 && tid < B_) g_cnt[tid] = 0;

    // distributed weight transposes (no same-launch reader -> race-free)
    if (sb < 192) {
        if (tid < 64) {
            g_wihT[tid * 192 + sb] = W_ih[sb * 64 + tid];
            g_whhT[tid * 192 + sb] = W_hh[sb * 64 + tid];
        }
    } else {
        int d = sb - 192;            // 0..63
        if (tid < 64) g_wkT[d * 64 + tid] = Wk[tid * 64 + d];
    }

    // copy this CTA's 2 slots
    {
        float v = slots_in[(b * NQ + 2 * p) * D + tid];
        s_sl[tid] = v;
        g_slots[(b * NQ + 2 * p) * D + tid] = v;
    }
    __syncthreads();

    // slot layernorm (warps 0,1 — one per slot)
    if (w < 2) {
        float x0 = s_sl[w * 64 + lane], x1 = s_sl[w * 64 + 32 + lane];
        float s = x0 + x1, qq = x0 * x0 + x1 * x1;
        #pragma unroll
        for (int off = 16; off; off >>= 1) {
            s  += __shfl_xor_sync(0xffffffffu, s,  off);
            qq += __shfl_xor_sync(0xffffffffu, qq, off);
        }
        float m = s * (1.f / 64.f);
        float rs = rsqrtf(qq * (1.f / 64.f) - m * m + 1e-5f);
        s_ln[w * 64 + lane]      = (x0 - m) * rs * lns_g[lane]      + lns_b[lane];
        s_ln[w * 64 + 32 + lane] = (x1 - m) * rs * lns_g[lane + 32] + lns_b[lane + 32];
    }
    __syncthreads();

    // qm = ln(slots) @ Wq  (one output per thread)
    {
        int qi = tid >> 6, e = tid & 63;
        const float* xl = s_ln + qi * 64;
        float acc = 0.f;
        #pragma unroll
        for (int dd = 0; dd < 64; dd++)
            acc = fmaf(xl[dd], Wq[dd * 64 + e], acc);
        s_qm[qi * 64 + e] = acc;
    }
    __syncthreads();

    // Wfold0 rows for this CTA: 8 c-rows x 32 bf16x2 cols (2 per thread)
    #pragma unroll
    for (int k = 0; k < 2; k++) {
        int o = tid + 128 * k;
        int lr = o >> 5, ep = o & 31;
        int h = lr >> 1, qi = lr & 1, q = 2 * p + qi, c = h * 8 + q;
        float a0 = 0.f, a1 = 0.f;
        #pragma unroll
        for (int dd = 0; dd < 16; dd++) {
            float qv = s_qm[qi * 64 + h * 16 + dd];
            a0 = fmaf(Wk[(2 * ep) * 64 + h * 16 + dd],     qv, a0);
            a1 = fmaf(Wk[(2 * ep + 1) * 64 + h * 16 + dd], qv, a1);
        }
        g_wfoldu[b * 1024 + c * 32 + ep] = pack_bf16x2(0.25f * a0, 0.25f * a1);
    }
}

// =====================================================================
// launcher: 4 launches
// =====================================================================
extern "C" void kernel_launch(void* const* d_in, const int* in_sizes, int n_in,
                              void* d_out, int out_size)
{
    const float* inputs = (const float*)d_in[0];
    const float* slots  = (const float*)d_in[1];
    const float* lnin_g = (const float*)d_in[2];
    const float* lnin_b = (const float*)d_in[3];
    const float* lns_g  = (const float*)d_in[4];
    const float* lns_b  = (const float*)d_in[5];
    const float* lnm_g  = (const float*)d_in[6];
    const float* lnm_b  = (const float*)d_in[7];
    const float* Wq     = (const float*)d_in[8];
    const float* Wk     = (const float*)d_in[9];
    const float* Wv     = (const float*)d_in[10];
    const float* W_ih   = (const float*)d_in[11];
    const float* W_hh   = (const float*)d_in[12];
    const float* b_ih   = (const float*)d_in[13];
    const float* b_hh   = (const float*)d_in[14];
    const float* W1     = (const float*)d_in[15];
    const float* b1     = (const float*)d_in[16];
    const float* W2     = (const float*)d_in[17];
    const float* b2     = (const float*)d_in[18];

    float* out       = (float*)d_out;
    float* out_slots = out;
    float* out_vis   = out + B_ * NQ * D;

    size_t smem = 2 * TT * SXF * 4 + TT * SXBU * 4 + TT * SATR * 2
                + C32 * WFU * 4 + 128 * 4;
    cudaFuncSetAttribute(vslot_main,
                         cudaFuncAttributeMaxDynamicSharedMemorySize, (int)smem);
    size_t smem_l = 2 * TT * SXBU * 4 + TT * SATR * 2 + C32 * WFU * 4;
    cudaFuncSetAttribute(vslot_lite,
                         cudaFuncAttributeMaxDynamicSharedMemorySize, (int)smem_l);

    vslot_init<<<NSLOT, 128>>>(slots, Wq, Wk, W_ih, W_hh, lns_g, lns_b);

    vslot_main<<<NMAIN0 + NSLOT, 128, smem>>>(
        inputs, lnin_g, lnin_b, /*tgt=*/NCH0,
        Wq, Wv, b_ih, b_hh, lns_g, lns_b, lnm_g, lnm_b,
        W1, b1, W2, b2, out_slots);

    vslot_lite<<<NMAIN1 + NSLOT, 128, smem_l>>>(
        out_vis, /*last=*/0, /*tgt=*/NCH0 + NCH1,
        Wq, Wv, b_ih, b_hh, lns_g, lns_b, lnm_g, lnm_b,
        W1, b1, W2, b2, out_slots);

    vslot_lite<<<NMAIN1 + NSLOT, 128, smem_l>>>(
        out_vis, /*last=*/1, /*tgt=*/NCH0 + 2 * NCH1,
        Wq, Wv, b_ih, b_hh, lns_g, lns_b, lnm_g, lnm_b,
        W1, b1, W2, b2, out_slots);
}